// round 3
// baseline (speedup 1.0000x reference)
#include <cuda_runtime.h>
#include <cstdint>

#define Bn 4
#define Ln 8192
#define Hn 128
#define Pn 64

typedef unsigned long long ull;

// Scratch (allocation-free rule: __device__ globals)
__device__ __align__(16) float g_Bu[Bn * Pn * Ln * 2];   // [b][p][l][(re,im)]
__device__ __align__(16) float g_ys[Bn * Pn * Ln * 2];   // [b][p][l][(re,im)]
__device__ __align__(16) float g_Bint[Pn * Hn * 2];      // [p][h][(re,im)]
__device__ __align__(16) float g_Cint[Hn * Pn * 2];      // [h][p][(re,-im)]

// ---------- packed f32x2 helpers ----------
__device__ __forceinline__ ull dup2(float v) {
    ull r; unsigned uv = __float_as_uint(v);
    asm("mov.b64 %0, {%1, %1};" : "=l"(r) : "r"(uv));
    return r;
}
__device__ __forceinline__ ull fma2(ull a, ull b, ull c) {
    ull d;
    asm("fma.rn.f32x2 %0, %1, %2, %3;" : "=l"(d) : "l"(a), "l"(b), "l"(c));
    return d;
}
__device__ __forceinline__ ull mul2(ull a, ull b) {
    ull d;
    asm("mul.rn.f32x2 %0, %1, %2;" : "=l"(d) : "l"(a), "l"(b));
    return d;
}
__device__ __forceinline__ void unpack2(ull v, float &lo, float &hi) {
    unsigned a, b;
    asm("mov.b64 {%0, %1}, %2;" : "=r"(a), "=r"(b) : "l"(v));
    lo = __uint_as_float(a); hi = __uint_as_float(b);
}

// ---------- Kernel 0: interleave weights ----------
__global__ __launch_bounds__(256) void k_prep(const float* __restrict__ Br,
                                              const float* __restrict__ Bi,
                                              const float* __restrict__ Cr,
                                              const float* __restrict__ Ci) {
    int i = blockIdx.x * 256 + threadIdx.x;    // 8192 elements each
    g_Bint[2 * i]     = Br[i];
    g_Bint[2 * i + 1] = Bi[i];
    g_Cint[2 * i]     = Cr[i];
    g_Cint[2 * i + 1] = -Ci[i];
}

// ---------- Kernel 1: Bu[b][p][l][c] = sum_h u[l,h] * B_c[p,h] ----------
// u transposed in smem; B streamed via LDG (L1-resident, 64 KB).
#define UP 68    // u smem pitch: [128 h][64 l + pad]

__global__ __launch_bounds__(256, 3) void k_gemmB(const float* __restrict__ u) {
    __shared__ float su[128 * UP];            // 34,816 B
    const int b = blockIdx.y, lt = blockIdx.x;   // Ltile = 64
    const int tid = threadIdx.x;

    const float* ug = u + ((size_t)b * Ln + (size_t)lt * 64) * Hn;
    for (int e = tid; e < 64 * Hn; e += 256) {
        int l = e >> 7, h = e & 127;
        su[h * UP + l] = ug[e];
    }
    __syncthreads();

    const int tx = tid & 7, ty = tid >> 3;      // ty 0..31
    const int lA = tx * 4, lB = 32 + tx * 4;
    const int p0 = ty * 2;

    ull accA[4][2], accB[4][2];
#pragma unroll
    for (int i = 0; i < 4; ++i) { accA[i][0]=0; accA[i][1]=0; accB[i][0]=0; accB[i][1]=0; }

    const float* suA = su + lA;
    const float* suB = su + lB;
    const ulonglong2* __restrict__ Bp0 = (const ulonglong2*)(g_Bint + p0 * 2 * Hn);
    const ulonglong2* __restrict__ Bp1 = (const ulonglong2*)(g_Bint + (p0 + 1) * 2 * Hn);

#pragma unroll 2
    for (int h = 0; h < Hn; h += 2) {
        float4 a0 = *(const float4*)(suA + h * UP);
        float4 a1 = *(const float4*)(suA + (h + 1) * UP);
        float4 c0 = *(const float4*)(suB + h * UP);
        float4 c1 = *(const float4*)(suB + (h + 1) * UP);
        ulonglong2 b0 = Bp0[h >> 1];   // (re,im) at h and h+1, row p0
        ulonglong2 b1 = Bp1[h >> 1];   // row p0+1
        ull dA0[4] = {dup2(a0.x), dup2(a0.y), dup2(a0.z), dup2(a0.w)};
        ull dA1[4] = {dup2(a1.x), dup2(a1.y), dup2(a1.z), dup2(a1.w)};
        ull dB0[4] = {dup2(c0.x), dup2(c0.y), dup2(c0.z), dup2(c0.w)};
        ull dB1[4] = {dup2(c1.x), dup2(c1.y), dup2(c1.z), dup2(c1.w)};
#pragma unroll
        for (int i = 0; i < 4; ++i) {
            accA[i][0] = fma2(dA0[i], b0.x, accA[i][0]);
            accA[i][0] = fma2(dA1[i], b0.y, accA[i][0]);
            accA[i][1] = fma2(dA0[i], b1.x, accA[i][1]);
            accA[i][1] = fma2(dA1[i], b1.y, accA[i][1]);
            accB[i][0] = fma2(dB0[i], b0.x, accB[i][0]);
            accB[i][0] = fma2(dB1[i], b0.y, accB[i][0]);
            accB[i][1] = fma2(dB0[i], b1.x, accB[i][1]);
            accB[i][1] = fma2(dB1[i], b1.y, accB[i][1]);
        }
    }

#pragma unroll
    for (int j = 0; j < 2; ++j) {
        int p = p0 + j;
        size_t base = ((size_t)(b * Pn + p) * Ln + (size_t)lt * 64) * 2;
        *(ulonglong2*)&g_Bu[base + 2 * lA]     = make_ulonglong2(accA[0][j], accA[1][j]);
        *(ulonglong2*)&g_Bu[base + 2 * lA + 4] = make_ulonglong2(accA[2][j], accA[3][j]);
        *(ulonglong2*)&g_Bu[base + 2 * lB]     = make_ulonglong2(accB[0][j], accB[1][j]);
        *(ulonglong2*)&g_Bu[base + 2 * lB + 4] = make_ulonglong2(accB[2][j], accB[3][j]);
    }
}

// ---------- Kernel 2: chunked linear-recurrence scan (f32x2 packed re/im) ----------
__global__ __launch_bounds__(512) void k_recur(const float* __restrict__ A_diag,
                                               const float* __restrict__ steps) {
    const int p = blockIdx.x, b = blockIdx.y;
    const int t = threadIdx.x;

    float a  = fmaxf(A_diag[p], 0.f);
    float s  = 1.f / (1.f + expf(-steps[p]));
    float s2a   = s * s * a;
    float schur = 1.f / (1.f + s2a);
    float m11 = 1.f - s2a * schur;
    float m12 = -s * a * schur;
    float m21 = s * schur;
    float m22 = schur;
    ull M11 = dup2(m11), M12 = dup2(m12), M21 = dup2(m21), M22 = dup2(m22);
    ull C1 = dup2(m11 * s), C2 = dup2(m21 * s);

    const size_t chain = (size_t)(b * Pn + p);
    const ulonglong2* src = (const ulonglong2*)(g_Bu) + chain * (Ln / 2) + t * 8;

    ull f[16];
#pragma unroll
    for (int k = 0; k < 8; ++k) {
        ulonglong2 v = src[k];
        f[2 * k] = v.x; f[2 * k + 1] = v.y;
    }

    // local pass from zero state
    ull z = 0, x = 0;
#pragma unroll
    for (int i = 0; i < 16; ++i) {
        ull nz = fma2(M11, z, fma2(M12, x, mul2(C1, f[i])));
        ull nx = fma2(M21, z, fma2(M22, x, mul2(C2, f[i])));
        z = nz; x = nx;
    }

    // M^16 by 4 squarings (scalar)
    float q00 = m11, q01 = m12, q10 = m21, q11 = m22;
#pragma unroll
    for (int k = 0; k < 4; ++k) {
        float n00 = q00*q00 + q01*q10, n01 = q00*q01 + q01*q11;
        float n10 = q10*q00 + q11*q10, n11 = q10*q01 + q11*q11;
        q00 = n00; q01 = n01; q10 = n10; q11 = n11;
    }

    // Hillis-Steele inclusive scan over 512 thread-segments
    __shared__ ulonglong2 sv[512];
    ull vz = z, vx = x;
    int off = 1;
#pragma unroll
    for (int st = 0; st < 9; ++st) {
        sv[t] = make_ulonglong2(vz, vx);
        __syncthreads();
        if (t >= off) {
            ulonglong2 w = sv[t - off];
            ull Q00 = dup2(q00), Q01 = dup2(q01), Q10 = dup2(q10), Q11 = dup2(q11);
            ull nvz = fma2(Q00, w.x, fma2(Q01, w.y, vz));
            ull nvx = fma2(Q10, w.x, fma2(Q11, w.y, vx));
            vz = nvz; vx = nvx;
        }
        __syncthreads();
        float n00 = q00*q00 + q01*q10, n01 = q00*q01 + q01*q11;
        float n10 = q10*q00 + q11*q10, n11 = q10*q01 + q11*q11;
        q00 = n00; q01 = n01; q10 = n10; q11 = n11;
        off <<= 1;
    }
    sv[t] = make_ulonglong2(vz, vx);
    __syncthreads();
    ull z0 = 0, x0 = 0;
    if (t > 0) { ulonglong2 w = sv[t - 1]; z0 = w.x; x0 = w.y; }

    // replay with correct start state; emit x (position) component
    z = z0; x = x0;
#pragma unroll
    for (int i = 0; i < 16; ++i) {
        ull nz = fma2(M11, z, fma2(M12, x, mul2(C1, f[i])));
        ull nx = fma2(M21, z, fma2(M22, x, mul2(C2, f[i])));
        z = nz; x = nx;
        f[i] = x;
    }
    ulonglong2* dst = (ulonglong2*)(g_ys) + chain * (Ln / 2) + t * 8;
#pragma unroll
    for (int k = 0; k < 8; ++k) dst[k] = make_ulonglong2(f[2 * k], f[2 * k + 1]);
}

// ---------- Kernel 3: y = ys_re @ Cr^T - ys_im @ Ci^T + D*u ----------
#define YPW 132   // sy pitch floats: [64 p][2l pairs + pad]
#define CPW 132   // sC pitch floats: [64 h][2p pairs + pad], holds (Cr, -Ci)

__global__ __launch_bounds__(256) void k_gemmD(const float* __restrict__ u,
                                               const float* __restrict__ Dv,
                                               float* __restrict__ out) {
    extern __shared__ float sm[];
    float* sy = sm;               // [64][YPW]
    float* sC = sm + Pn * YPW;    // [64][CPW]
    const int b = blockIdx.y, lt = blockIdx.x, hh = blockIdx.z;   // Ltile=64, Htile=64
    const int tid = threadIdx.x;

    // stage ys tile: 64 p x 64 l pairs (vector copies)
    for (int e = tid; e < Pn * 32; e += 256) {
        int p = e >> 5, g = e & 31;
        const ulonglong2* yg = (const ulonglong2*)(g_ys) +
            ((size_t)(b * Pn + p) * Ln + (size_t)lt * 64) / 2 + g;
        *(ulonglong2*)&sy[p * YPW + 4 * g] = *yg;
    }
    // stage C tile from interleaved g_Cint (vector copies)
    for (int e = tid; e < 64 * 32; e += 256) {
        int h = e >> 5, g = e & 31;
        const ulonglong2* cg = (const ulonglong2*)(g_Cint) +
            ((size_t)(hh * 64 + h) * Pn) / 2 + g;
        *(ulonglong2*)&sC[h * CPW + 4 * g] = *cg;
    }
    __syncthreads();

    const int tx = tid & 15, ty = tid >> 4;    // 16 x 16
    const int lA = 2 * tx, lB = 32 + 2 * tx;
    const int hl = 4 * ty;

    ull accA[2][4], accB[2][4];
#pragma unroll
    for (int i = 0; i < 2; ++i)
#pragma unroll
        for (int j = 0; j < 4; ++j) { accA[i][j] = 0; accB[i][j] = 0; }

#pragma unroll 2
    for (int p = 0; p < Pn; p += 2) {
        ulonglong2 yA0 = *(const ulonglong2*)&sy[p * YPW + 2 * lA];
        ulonglong2 yA1 = *(const ulonglong2*)&sy[(p + 1) * YPW + 2 * lA];
        ulonglong2 yB0 = *(const ulonglong2*)&sy[p * YPW + 2 * lB];
        ulonglong2 yB1 = *(const ulonglong2*)&sy[(p + 1) * YPW + 2 * lB];
#pragma unroll
        for (int j = 0; j < 4; ++j) {
            ulonglong2 cj = *(const ulonglong2*)&sC[(hl + j) * CPW + 2 * p];
            accA[0][j] = fma2(yA0.x, cj.x, accA[0][j]);
            accA[0][j] = fma2(yA1.x, cj.y, accA[0][j]);
            accA[1][j] = fma2(yA0.y, cj.x, accA[1][j]);
            accA[1][j] = fma2(yA1.y, cj.y, accA[1][j]);
            accB[0][j] = fma2(yB0.x, cj.x, accB[0][j]);
            accB[0][j] = fma2(yB1.x, cj.y, accB[0][j]);
            accB[1][j] = fma2(yB0.y, cj.x, accB[1][j]);
            accB[1][j] = fma2(yB1.y, cj.y, accB[1][j]);
        }
    }

    const int h0 = hh * 64 + hl;
    float4 dv4 = *(const float4*)&Dv[h0];
    float dv[4] = {dv4.x, dv4.y, dv4.z, dv4.w};

#pragma unroll
    for (int g = 0; g < 4; ++g) {
        int l = (g < 2) ? (lA + g) : (lB + (g - 2));
        ull* arow = (g < 2) ? accA[g] : accB[g - 2];
        size_t row = ((size_t)b * Ln + (size_t)lt * 64 + l) * Hn + h0;
        float4 uu = *(const float4*)&u[row];
        float uv[4] = {uu.x, uu.y, uu.z, uu.w};
        float y[4];
#pragma unroll
        for (int j = 0; j < 4; ++j) {
            float lo, hi; unpack2(arow[j], lo, hi);
            y[j] = lo + hi + dv[j] * uv[j];
        }
        *(float4*)&out[row] = make_float4(y[0], y[1], y[2], y[3]);
    }
}

// ---------- launch ----------
extern "C" void kernel_launch(void* const* d_in, const int* in_sizes, int n_in,
                              void* d_out, int out_size) {
    const float* u     = (const float*)d_in[0];
    const float* A_d   = (const float*)d_in[1];
    const float* Br    = (const float*)d_in[2];
    const float* Bi    = (const float*)d_in[3];
    const float* Cr    = (const float*)d_in[4];
    const float* Ci    = (const float*)d_in[5];
    const float* Dv    = (const float*)d_in[6];
    const float* steps = (const float*)d_in[7];
    float* out = (float*)d_out;

    const int SMD = (Pn * YPW + 64 * CPW) * 4;   // 67,584 B -> 3 blocks/SM
    cudaFuncSetAttribute(k_gemmD, cudaFuncAttributeMaxDynamicSharedMemorySize, SMD);

    k_prep<<<32, 256>>>(Br, Bi, Cr, Ci);
    k_gemmB<<<dim3(Ln / 64, Bn), 256>>>(u);
    k_recur<<<dim3(Pn, Bn), 512>>>(A_d, steps);
    k_gemmD<<<dim3(Ln / 64, Bn, 2), 256, SMD>>>(u, Dv, out);
}